// round 6
// baseline (speedup 1.0000x reference)
#include <cuda_runtime.h>
#include <cuda_fp16.h>
#include <cuda_bf16.h>

// Problem constants
#define NNODES 50000
#define NEDGES 800000
#define IN_DIM 256
#define HDIM   128
#define H2DIM  64
#define ODIM   32
#define KHOPS  5
#define EPS    1e-5f

#define NBLOCKS 592           // 148 SMs x 4 co-resident blocks (guaranteed)
#define NWARPS  (NBLOCKS * 8) // persistent warps

// ---------------------------------------------------------------------------
// Scratch (device globals; no allocation allowed)
// ---------------------------------------------------------------------------
__device__ float  gB1[NNODES * HDIM];      // GEMM1 output
__device__ float  gFz[NNODES * HDIM];      // fused accumulator
__device__ __half gH0[NNODES * HDIM];      // fp16 state buffers (rotating)
__device__ __half gH1[NNODES * HDIM];
__device__ __half gH2[NNODES * HDIM];
__device__ float  gWsum[NNODES];
__device__ int    gDeg[NNODES];
__device__ int    gCur[NNODES];
__device__ int    gOff[NNODES + 1];
__device__ int2   gEdge[NEDGES];           // {src, __float_as_int(weight)}
__device__ float  gSw[8];
__device__ unsigned          gBarCnt;
__device__ volatile unsigned gBarGen;

// ---------------------------------------------------------------------------
// Tiled fp32 GEMM.
// FUSEP=false: out32 = relu(bn(A@W+b))
// FUSEP=true : t = relu(bn(A@W+b)) + ident; out16 = fp16(t); F = sw[0]*t
// ---------------------------------------------------------------------------
template <int KDIM, bool RES, bool FUSEP>
__global__ void gemm_bn_relu(const float* __restrict__ A,
                             const float* __restrict__ W,
                             const float* __restrict__ bias,
                             const float* __restrict__ g,
                             const float* __restrict__ be,
                             const float* __restrict__ m,
                             const float* __restrict__ v,
                             const float* __restrict__ ident,
                             float* __restrict__ out32,
                             __half* __restrict__ out16,
                             float* __restrict__ F,
                             const float* __restrict__ sw, int M) {
    __shared__ float  As[64][17];
    __shared__ float4 Bs[16][32];
    const int tid = threadIdx.x;
    const int rowBase = blockIdx.x * 64;
    const int cg = tid & 31;
    const int rg = tid >> 5;

    float acc[8][4];
#pragma unroll
    for (int i = 0; i < 8; i++)
#pragma unroll
        for (int j = 0; j < 4; j++) acc[i][j] = 0.f;

    for (int k0 = 0; k0 < KDIM; k0 += 16) {
        {
            int r = tid >> 2, c4 = tid & 3;
            float4 val = make_float4(0.f, 0.f, 0.f, 0.f);
            if (rowBase + r < M)
                val = *(const float4*)(A + (size_t)(rowBase + r) * KDIM + k0 + c4 * 4);
            As[r][c4 * 4 + 0] = val.x; As[r][c4 * 4 + 1] = val.y;
            As[r][c4 * 4 + 2] = val.z; As[r][c4 * 4 + 3] = val.w;
        }
#pragma unroll
        for (int i = tid; i < 512; i += 256) {
            int r = i >> 5, c = i & 31;
            Bs[r][c] = *(const float4*)(W + (size_t)(k0 + r) * HDIM + c * 4);
        }
        __syncthreads();
#pragma unroll
        for (int kk = 0; kk < 16; kk++) {
            float a[8];
#pragma unroll
            for (int i = 0; i < 8; i++) a[i] = As[rg * 8 + i][kk];
            float4 b = Bs[kk][cg];
#pragma unroll
            for (int i = 0; i < 8; i++) {
                acc[i][0] += a[i] * b.x; acc[i][1] += a[i] * b.y;
                acc[i][2] += a[i] * b.z; acc[i][3] += a[i] * b.w;
            }
        }
        __syncthreads();
    }

    float s[4], sh[4], bb[4];
#pragma unroll
    for (int j = 0; j < 4; j++) {
        int c = cg * 4 + j;
        s[j]  = g[c] * rsqrtf(v[c] + EPS);
        sh[j] = be[c] - m[c] * s[j];
        bb[j] = bias[c];
    }
    float fw = FUSEP ? __ldg(sw) : 0.f;
#pragma unroll
    for (int i = 0; i < 8; i++) {
        int rr = rowBase + rg * 8 + i;
        if (rr < M) {
            float4 o;
            o.x = fmaxf((acc[i][0] + bb[0]) * s[0] + sh[0], 0.f);
            o.y = fmaxf((acc[i][1] + bb[1]) * s[1] + sh[1], 0.f);
            o.z = fmaxf((acc[i][2] + bb[2]) * s[2] + sh[2], 0.f);
            o.w = fmaxf((acc[i][3] + bb[3]) * s[3] + sh[3], 0.f);
            if (RES) {
                float4 r4 = *(const float4*)(ident + (size_t)rr * HDIM + cg * 4);
                o.x += r4.x; o.y += r4.y; o.z += r4.z; o.w += r4.w;
            }
            if (FUSEP) {
                __half2 h0 = __floats2half2_rn(o.x, o.y);
                __half2 h1 = __floats2half2_rn(o.z, o.w);
                uint2 hv = make_uint2(*(unsigned*)&h0, *(unsigned*)&h1);
                ((uint2*)(out16 + (size_t)rr * HDIM))[cg] = hv;
                float4 f = make_float4(fw * o.x, fw * o.y, fw * o.z, fw * o.w);
                *(float4*)(F + (size_t)rr * HDIM + cg * 4) = f;
            } else {
                *(float4*)(out32 + (size_t)rr * HDIM + cg * 4) = o;
            }
        }
    }
}

// ---------------------------------------------------------------------------
// CSC build
// ---------------------------------------------------------------------------
__global__ void zero_ws_deg(float* __restrict__ ws, int* __restrict__ deg) {
    int i = blockIdx.x * blockDim.x + threadIdx.x;
    if (i < NNODES) { ws[i] = 0.f; deg[i] = 0; }
}

__global__ void wsum_deg_kernel(const int* __restrict__ row,
                                const int* __restrict__ col,
                                const float* __restrict__ w,
                                float* __restrict__ ws,
                                int* __restrict__ deg) {
    int i = blockIdx.x * blockDim.x + threadIdx.x;
    if (i < NEDGES) {
        atomicAdd(&ws[row[i]], w[i]);
        atomicAdd(&deg[col[i]], 1);
    }
}

__global__ void scan_offsets(const int* __restrict__ deg,
                             int* __restrict__ off,
                             int* __restrict__ cursor) {
    __shared__ int partial[1024];
    const int CH = (NNODES + 1023) / 1024;
    int tid = threadIdx.x;
    int start = tid * CH;
    int sum = 0;
    for (int j = 0; j < CH; j++) {
        int idx = start + j;
        if (idx < NNODES) sum += deg[idx];
    }
    partial[tid] = sum;
    __syncthreads();
    for (int d = 1; d < 1024; d <<= 1) {
        int t = (tid >= d) ? partial[tid - d] : 0;
        __syncthreads();
        partial[tid] += t;
        __syncthreads();
    }
    int run = (tid == 0) ? 0 : partial[tid - 1];
    for (int j = 0; j < CH; j++) {
        int idx = start + j;
        if (idx < NNODES) {
            off[idx] = run;
            cursor[idx] = run;
            run += deg[idx];
        }
    }
    if (tid == 1023) off[NNODES] = NEDGES;
}

__global__ void fill_csc(const int* __restrict__ row,
                         const int* __restrict__ col,
                         const float* __restrict__ w,
                         const float* __restrict__ ws,
                         int* __restrict__ cursor,
                         int2* __restrict__ edge) {
    int i = blockIdx.x * blockDim.x + threadIdx.x;
    if (i < NEDGES) {
        int r = row[i];
        int c = col[i];
        float wn = 0.9f * w[i] / fmaxf(ws[r], 1.0f);
        int pos = atomicAdd(&cursor[c], 1);
        edge[pos] = make_int2(r, __float_as_int(wn));
    }
}

// Also resets the grid-barrier state each launch (graph replay safe).
__global__ void softmax6(const float* __restrict__ att, float* __restrict__ sw) {
    if (threadIdx.x == 0 && blockIdx.x == 0) {
        gBarCnt = 0u;
        gBarGen = 0u;
        float mx = -1e30f;
        for (int i = 0; i < KHOPS + 1; i++) mx = fmaxf(mx, att[i]);
        float e[KHOPS + 1], sum = 0.f;
        for (int i = 0; i < KHOPS + 1; i++) { e[i] = expf(att[i] - mx); sum += e[i]; }
        for (int i = 0; i < KHOPS + 1; i++) sw[i] = e[i] / sum;
    }
}

// ---------------------------------------------------------------------------
// Software grid barrier (all NBLOCKS blocks are co-resident by launch bounds)
// ---------------------------------------------------------------------------
__device__ __forceinline__ void grid_barrier(unsigned gen) {
    __syncthreads();
    if (threadIdx.x == 0) {
        __threadfence();
        unsigned t = atomicAdd(&gBarCnt, 1u);
        if (t == (unsigned)NBLOCKS - 1u) {
            gBarCnt = 0u;
            __threadfence();
            gBarGen = gen;
        } else {
            while (gBarGen < gen) __nanosleep(64);
            __threadfence();
        }
    }
    __syncthreads();
}

// ---------------------------------------------------------------------------
// Persistent propagation: all 25 gather steps in one kernel.
// Per node: acc = 0.1*anc16[n] + sum_e w_e * src16[esrc_e]  (fp32 accumulate)
// Half-warp per edge, LDG.128 rows via L2-only (__ldcg) to keep edges in L1.
// ---------------------------------------------------------------------------
__device__ __forceinline__ void acc8(float* a, uint4 p, float wgt) {
    float2 t0 = __half22float2(*(__half2*)&p.x);
    float2 t1 = __half22float2(*(__half2*)&p.y);
    float2 t2 = __half22float2(*(__half2*)&p.z);
    float2 t3 = __half22float2(*(__half2*)&p.w);
    a[0] += wgt * t0.x; a[1] += wgt * t0.y;
    a[2] += wgt * t1.x; a[3] += wgt * t1.y;
    a[4] += wgt * t2.x; a[5] += wgt * t2.y;
    a[6] += wgt * t3.x; a[7] += wgt * t3.y;
}

__device__ __forceinline__ void gather_node(
    int n, int lane, int halfe, int hl,
    const __half* __restrict__ src16,
    const __half* __restrict__ anc16,
    __half* __restrict__ dst16,
    const int* __restrict__ off,
    const int2* __restrict__ edge,
    float* __restrict__ F,
    float fw, bool fin, bool writeDst) {

    int s = __ldg(off + n);
    int e = __ldg(off + n + 1);
    int npair = (e - s + 1) >> 1;

    float a[8];
#pragma unroll
    for (int j = 0; j < 8; j++) a[j] = 0.f;

    int it = 0;
    for (; it + 4 <= npair; it += 4) {
        int b0 = s + 2 * it + halfe;
        int2 e0 = (b0     < e) ? __ldg(edge + b0)     : make_int2(0, 0);
        int2 e1 = (b0 + 2 < e) ? __ldg(edge + b0 + 2) : make_int2(0, 0);
        int2 e2 = (b0 + 4 < e) ? __ldg(edge + b0 + 4) : make_int2(0, 0);
        int2 e3 = (b0 + 6 < e) ? __ldg(edge + b0 + 6) : make_int2(0, 0);
        uint4 p0 = __ldcg((const uint4*)(src16 + (size_t)e0.x * HDIM) + hl);
        uint4 p1 = __ldcg((const uint4*)(src16 + (size_t)e1.x * HDIM) + hl);
        uint4 p2 = __ldcg((const uint4*)(src16 + (size_t)e2.x * HDIM) + hl);
        uint4 p3 = __ldcg((const uint4*)(src16 + (size_t)e3.x * HDIM) + hl);
        acc8(a, p0, __int_as_float(e0.y));
        acc8(a, p1, __int_as_float(e1.y));
        acc8(a, p2, __int_as_float(e2.y));
        acc8(a, p3, __int_as_float(e3.y));
    }
    for (; it < npair; it++) {
        int b0 = s + 2 * it + halfe;
        int2 e0 = (b0 < e) ? __ldg(edge + b0) : make_int2(0, 0);
        uint4 p0 = __ldcg((const uint4*)(src16 + (size_t)e0.x * HDIM) + hl);
        acc8(a, p0, __int_as_float(e0.y));
    }

#pragma unroll
    for (int j = 0; j < 8; j++)
        a[j] += __shfl_down_sync(0xffffffffu, a[j], 16);

    if (halfe == 0) {
        uint4 hp = __ldcg((const uint4*)(anc16 + (size_t)n * HDIM) + hl);
        float2 h0 = __half22float2(*(__half2*)&hp.x);
        float2 h1 = __half22float2(*(__half2*)&hp.y);
        float2 h2 = __half22float2(*(__half2*)&hp.z);
        float2 h3 = __half22float2(*(__half2*)&hp.w);
        a[0] += 0.1f * h0.x; a[1] += 0.1f * h0.y;
        a[2] += 0.1f * h1.x; a[3] += 0.1f * h1.y;
        a[4] += 0.1f * h2.x; a[5] += 0.1f * h2.y;
        a[6] += 0.1f * h3.x; a[7] += 0.1f * h3.y;

        if (writeDst) {
            __half2 o0 = __floats2half2_rn(a[0], a[1]);
            __half2 o1 = __floats2half2_rn(a[2], a[3]);
            __half2 o2 = __floats2half2_rn(a[4], a[5]);
            __half2 o3 = __floats2half2_rn(a[6], a[7]);
            uint4 ov = make_uint4(*(unsigned*)&o0, *(unsigned*)&o1,
                                  *(unsigned*)&o2, *(unsigned*)&o3);
            *((uint4*)(dst16 + (size_t)n * HDIM) + hl) = ov;
        }
        if (fin) {
            float4* fp = (float4*)(F + (size_t)n * HDIM) + hl * 2;
            float4 f0 = __ldcg(fp), f1 = __ldcg(fp + 1);
            f0.x += fw * a[0]; f0.y += fw * a[1]; f0.z += fw * a[2]; f0.w += fw * a[3];
            f1.x += fw * a[4]; f1.y += fw * a[5]; f1.z += fw * a[6]; f1.w += fw * a[7];
            fp[0] = f0; fp[1] = f1;
        }
    }
}

__global__ void __launch_bounds__(256, 4)
prop_persist(__half* __restrict__ hb0,
             __half* __restrict__ hb1,
             __half* __restrict__ hb2,
             const int* __restrict__ off,
             const int2* __restrict__ edge,
             float* __restrict__ F,
             const float* __restrict__ sw) {
    __half* bufs[3] = {hb0, hb1, hb2};
    const int gw    = blockIdx.x * 8 + (threadIdx.x >> 5);
    const int lane  = threadIdx.x & 31;
    const int halfe = lane >> 4;
    const int hl    = lane & 15;

    int anci = 0, curi = 0;
    unsigned gen = 0;

    for (int k = 0; k < KHOPS; k++) {
        anci = curi;
        for (int t = 0; t < KHOPS; t++) {
            int dsti = 0;
            for (int d = 0; d < 3; d++)
                if (d != anci && d != curi) dsti = d;

            const __half* srcp = bufs[curi];
            const __half* ancp = bufs[anci];
            __half*       dstp = bufs[dsti];
            bool fin      = (t == KHOPS - 1);
            bool writeDst = !(fin && k == KHOPS - 1);
            float fw = fin ? __ldg(sw + k + 1) : 0.f;

            for (int n = gw; n < NNODES; n += NWARPS)
                gather_node(n, lane, halfe, hl, srcp, ancp, dstp,
                            off, edge, F, fw, fin, writeDst);

            curi = dsti;
            if (!(k == KHOPS - 1 && t == KHOPS - 1)) {
                gen++;
                grid_barrier(gen);
            }
        }
    }
}

// ---------------------------------------------------------------------------
// Head: out = relu(bn3(F@W3 + b3)) @ W4 + b4   — one warp per node
// ---------------------------------------------------------------------------
__global__ void head_kernel(const float* __restrict__ F,
                            const float* __restrict__ W3, const float* __restrict__ b3,
                            const float* __restrict__ g3, const float* __restrict__ be3,
                            const float* __restrict__ m3, const float* __restrict__ v3,
                            const float* __restrict__ W4, const float* __restrict__ b4,
                            float* __restrict__ out) {
    __shared__ float sW3[HDIM * H2DIM];
    __shared__ float sW4[H2DIM * ODIM];
    __shared__ float sS3[H2DIM], sSh3[H2DIM], sB4[ODIM];
    __shared__ float fr[8][HDIM];
    __shared__ float hid[8][H2DIM];

    int tid = threadIdx.x;
    for (int i = tid; i < HDIM * H2DIM; i += blockDim.x) sW3[i] = W3[i];
    for (int i = tid; i < H2DIM * ODIM; i += blockDim.x) sW4[i] = W4[i];
    if (tid < H2DIM) {
        float s = g3[tid] * rsqrtf(v3[tid] + EPS);
        sS3[tid] = s;
        sSh3[tid] = (b3[tid] - m3[tid]) * s + be3[tid];
    }
    if (tid < ODIM) sB4[tid] = b4[tid];
    __syncthreads();

    int warp = tid >> 5, lane = tid & 31;
    int nwarps = blockDim.x >> 5;
    for (int n = blockIdx.x * nwarps + warp; n < NNODES; n += gridDim.x * nwarps) {
        ((float4*)fr[warp])[lane] = ((const float4*)(F + (size_t)n * HDIM))[lane];
        __syncwarp();
#pragma unroll
        for (int hh = 0; hh < 2; hh++) {
            int j = lane + 32 * hh;
            float acc = 0.f;
#pragma unroll 8
            for (int k = 0; k < HDIM; k++) acc += fr[warp][k] * sW3[k * H2DIM + j];
            hid[warp][j] = fmaxf(acc * sS3[j] + sSh3[j], 0.f);
        }
        __syncwarp();
        float acc = sB4[lane];
#pragma unroll 8
        for (int j = 0; j < H2DIM; j++) acc += hid[warp][j] * sW4[j * ODIM + lane];
        out[(size_t)n * ODIM + lane] = acc;
        __syncwarp();
    }
}

// ---------------------------------------------------------------------------
// Launch
// ---------------------------------------------------------------------------
extern "C" void kernel_launch(void* const* d_in, const int* in_sizes, int n_in,
                              void* d_out, int out_size) {
    const float* x   = (const float*)d_in[0];
    const int*   ei  = (const int*)d_in[1];
    const float* ew  = (const float*)d_in[2];
    const float* W1  = (const float*)d_in[3];
    const float* b1  = (const float*)d_in[4];
    const float* g1  = (const float*)d_in[5];
    const float* be1 = (const float*)d_in[6];
    const float* m1  = (const float*)d_in[7];
    const float* v1  = (const float*)d_in[8];
    const float* W2  = (const float*)d_in[9];
    const float* b2  = (const float*)d_in[10];
    const float* g2  = (const float*)d_in[11];
    const float* be2 = (const float*)d_in[12];
    const float* m2  = (const float*)d_in[13];
    const float* v2  = (const float*)d_in[14];
    const float* att = (const float*)d_in[15];
    const float* W3  = (const float*)d_in[16];
    const float* b3  = (const float*)d_in[17];
    const float* g3  = (const float*)d_in[18];
    const float* be3 = (const float*)d_in[19];
    const float* m3  = (const float*)d_in[20];
    const float* v3  = (const float*)d_in[21];
    const float* W4  = (const float*)d_in[22];
    const float* b4  = (const float*)d_in[23];

    const int* row = ei;
    const int* col = ei + NEDGES;

    float *B1, *F, *WS, *SW;
    __half* HB[3];
    int *DEG, *CUR, *OFF;
    int2 *EDGE;
    cudaGetSymbolAddress((void**)&B1,    gB1);
    cudaGetSymbolAddress((void**)&F,     gFz);
    cudaGetSymbolAddress((void**)&HB[0], gH0);
    cudaGetSymbolAddress((void**)&HB[1], gH1);
    cudaGetSymbolAddress((void**)&HB[2], gH2);
    cudaGetSymbolAddress((void**)&WS,    gWsum);
    cudaGetSymbolAddress((void**)&DEG,   gDeg);
    cudaGetSymbolAddress((void**)&CUR,   gCur);
    cudaGetSymbolAddress((void**)&OFF,   gOff);
    cudaGetSymbolAddress((void**)&EDGE,  gEdge);
    cudaGetSymbolAddress((void**)&SW,    gSw);

    const int gemmBlocks = (NNODES + 63) / 64;
    const int edgeBlocks = (NEDGES + 255) / 256;

    // Feature MLP. GEMM2 emits fp16 state (buffer 0) + F = sw[0]*hc.
    softmax6<<<1, 32>>>(att, SW);   // also resets grid barrier
    gemm_bn_relu<IN_DIM, false, false><<<gemmBlocks, 256>>>(
        x,  W1, b1, g1, be1, m1, v1, nullptr, B1, nullptr, nullptr, nullptr, NNODES);
    gemm_bn_relu<HDIM,   true,  true ><<<gemmBlocks, 256>>>(
        B1, W2, b2, g2, be2, m2, v2, B1, nullptr, HB[0], F, SW, NNODES);

    // CSC build
    zero_ws_deg<<<(NNODES + 255) / 256, 256>>>(WS, DEG);
    wsum_deg_kernel<<<edgeBlocks, 256>>>(row, col, ew, WS, DEG);
    scan_offsets<<<1, 1024>>>(DEG, OFF, CUR);
    fill_csc<<<edgeBlocks, 256>>>(row, col, ew, WS, CUR, EDGE);

    // All 25 propagation steps in one persistent kernel
    prop_persist<<<NBLOCKS, 256>>>(HB[0], HB[1], HB[2], OFF, EDGE, F, SW);

    // Head
    head_kernel<<<1184, 256>>>(F, W3, b3, g3, be3, m3, v3, W4, b4, (float*)d_out);
}

// round 7
// speedup vs baseline: 1.0246x; 1.0246x over previous
#include <cuda_runtime.h>
#include <cuda_fp16.h>
#include <cuda_bf16.h>

// Problem constants
#define NNODES 50000
#define NEDGES 800000
#define IN_DIM 256
#define HDIM   128
#define H2DIM  64
#define ODIM   32
#define KHOPS  5
#define EPS    1e-5f

#define GEMM_BLOCKS ((NNODES + 63) / 64)   // 782
#define WS_BLOCKS   160                    // extra blocks in K1 for wsum/deg

// ---------------------------------------------------------------------------
// Scratch (device globals; zero-initialized at module load).
// gWsum/gDeg are re-zeroed at the END of every launch (in head_kernel) so the
// zero-state invariant holds across graph replays.
// ---------------------------------------------------------------------------
__device__ float  gB1[NNODES * HDIM];      // GEMM1 output
__device__ float  gFz[NNODES * HDIM];      // fused accumulator
__device__ __half gH0[NNODES * HDIM];      // fp16 state buffers (rotating)
__device__ __half gH1[NNODES * HDIM];
__device__ __half gH2[NNODES * HDIM];
__device__ float  gWsum[NNODES];
__device__ int    gDeg[NNODES];
__device__ int    gCur[NNODES];
__device__ int    gOff[NNODES + 1];
__device__ int2   gEdge[NEDGES];           // {src, __float_as_int(weight)}
__device__ float  gSw[8];

// ---------------------------------------------------------------------------
// Tiled fp32 GEMM body (device function; block role decided by caller).
// FUSEP=false: out32 = relu(bn(A@W+b))
// FUSEP=true : t = relu(bn(A@W+b)) + ident; out16 = fp16(t); F = sw[0]*t
// ---------------------------------------------------------------------------
template <int KDIM, bool RES, bool FUSEP>
__device__ __forceinline__ void gemm_body(
    int bx,
    const float* __restrict__ A,
    const float* __restrict__ W,
    const float* __restrict__ bias,
    const float* __restrict__ g,
    const float* __restrict__ be,
    const float* __restrict__ m,
    const float* __restrict__ v,
    const float* __restrict__ ident,
    float* __restrict__ out32,
    __half* __restrict__ out16,
    float* __restrict__ F,
    const float* __restrict__ sw, int M) {
    __shared__ float  As[64][17];
    __shared__ float4 Bs[16][32];
    const int tid = threadIdx.x;
    const int rowBase = bx * 64;
    const int cg = tid & 31;
    const int rg = tid >> 5;

    float acc[8][4];
#pragma unroll
    for (int i = 0; i < 8; i++)
#pragma unroll
        for (int j = 0; j < 4; j++) acc[i][j] = 0.f;

    for (int k0 = 0; k0 < KDIM; k0 += 16) {
        {
            int r = tid >> 2, c4 = tid & 3;
            float4 val = make_float4(0.f, 0.f, 0.f, 0.f);
            if (rowBase + r < M)
                val = *(const float4*)(A + (size_t)(rowBase + r) * KDIM + k0 + c4 * 4);
            As[r][c4 * 4 + 0] = val.x; As[r][c4 * 4 + 1] = val.y;
            As[r][c4 * 4 + 2] = val.z; As[r][c4 * 4 + 3] = val.w;
        }
#pragma unroll
        for (int i = tid; i < 512; i += 256) {
            int r = i >> 5, c = i & 31;
            Bs[r][c] = *(const float4*)(W + (size_t)(k0 + r) * HDIM + c * 4);
        }
        __syncthreads();
#pragma unroll
        for (int kk = 0; kk < 16; kk++) {
            float a[8];
#pragma unroll
            for (int i = 0; i < 8; i++) a[i] = As[rg * 8 + i][kk];
            float4 b = Bs[kk][cg];
#pragma unroll
            for (int i = 0; i < 8; i++) {
                acc[i][0] += a[i] * b.x; acc[i][1] += a[i] * b.y;
                acc[i][2] += a[i] * b.z; acc[i][3] += a[i] * b.w;
            }
        }
        __syncthreads();
    }

    float s[4], sh[4], bb[4];
#pragma unroll
    for (int j = 0; j < 4; j++) {
        int c = cg * 4 + j;
        s[j]  = g[c] * rsqrtf(v[c] + EPS);
        sh[j] = be[c] - m[c] * s[j];
        bb[j] = bias[c];
    }
    float fw = FUSEP ? __ldg(sw) : 0.f;
#pragma unroll
    for (int i = 0; i < 8; i++) {
        int rr = rowBase + rg * 8 + i;
        if (rr < M) {
            float4 o;
            o.x = fmaxf((acc[i][0] + bb[0]) * s[0] + sh[0], 0.f);
            o.y = fmaxf((acc[i][1] + bb[1]) * s[1] + sh[1], 0.f);
            o.z = fmaxf((acc[i][2] + bb[2]) * s[2] + sh[2], 0.f);
            o.w = fmaxf((acc[i][3] + bb[3]) * s[3] + sh[3], 0.f);
            if (RES) {
                float4 r4 = *(const float4*)(ident + (size_t)rr * HDIM + cg * 4);
                o.x += r4.x; o.y += r4.y; o.z += r4.z; o.w += r4.w;
            }
            if (FUSEP) {
                __half2 h0 = __floats2half2_rn(o.x, o.y);
                __half2 h1 = __floats2half2_rn(o.z, o.w);
                uint2 hv = make_uint2(*(unsigned*)&h0, *(unsigned*)&h1);
                ((uint2*)(out16 + (size_t)rr * HDIM))[cg] = hv;
                float4 f = make_float4(fw * o.x, fw * o.y, fw * o.z, fw * o.w);
                *(float4*)(F + (size_t)rr * HDIM + cg * 4) = f;
            } else {
                *(float4*)(out32 + (size_t)rr * HDIM + cg * 4) = o;
            }
        }
    }
}

// ---------------------------------------------------------------------------
// K1: GEMM1 + (tail blocks) wsum/deg accumulation + softmax(att)
// ---------------------------------------------------------------------------
__global__ void k1_gemm1_wsum(const float* __restrict__ x,
                              const float* __restrict__ W1,
                              const float* __restrict__ b1,
                              const float* __restrict__ g1,
                              const float* __restrict__ be1,
                              const float* __restrict__ m1,
                              const float* __restrict__ v1,
                              float* __restrict__ out32,
                              const int* __restrict__ row,
                              const int* __restrict__ col,
                              const float* __restrict__ ew,
                              float* __restrict__ ws,
                              int* __restrict__ deg,
                              const float* __restrict__ att,
                              float* __restrict__ sw) {
    int bx = blockIdx.x;
    if (bx < GEMM_BLOCKS) {
        gemm_body<IN_DIM, false, false>(bx, x, W1, b1, g1, be1, m1, v1,
                                        nullptr, out32, nullptr, nullptr, nullptr, NNODES);
        return;
    }
    // wsum/deg tail blocks
    int ebx = bx - GEMM_BLOCKS;
    for (int i = ebx * 256 + threadIdx.x; i < NEDGES; i += WS_BLOCKS * 256) {
        atomicAdd(&ws[row[i]], ew[i]);
        atomicAdd(&deg[col[i]], 1);
    }
    if (ebx == WS_BLOCKS - 1 && threadIdx.x == 0) {
        float mx = -1e30f;
        for (int i = 0; i < KHOPS + 1; i++) mx = fmaxf(mx, att[i]);
        float e[KHOPS + 1], sum = 0.f;
        for (int i = 0; i < KHOPS + 1; i++) { e[i] = expf(att[i] - mx); sum += e[i]; }
        for (int i = 0; i < KHOPS + 1; i++) sw[i] = e[i] / sum;
    }
}

// ---------------------------------------------------------------------------
// K2: GEMM2 (+ fp16 state + F init) + (1 tail block) offset scan
// ---------------------------------------------------------------------------
__global__ void k2_gemm2_scan(const float* __restrict__ h1,
                              const float* __restrict__ W2,
                              const float* __restrict__ b2,
                              const float* __restrict__ g2,
                              const float* __restrict__ be2,
                              const float* __restrict__ m2,
                              const float* __restrict__ v2,
                              __half* __restrict__ out16,
                              float* __restrict__ F,
                              const float* __restrict__ sw,
                              const int* __restrict__ deg,
                              int* __restrict__ off,
                              int* __restrict__ cursor) {
    int bx = blockIdx.x;
    if (bx < GEMM_BLOCKS) {
        gemm_body<HDIM, true, true>(bx, h1, W2, b2, g2, be2, m2, v2,
                                    h1, nullptr, out16, F, sw, NNODES);
        return;
    }
    // single tail block: exclusive scan of degrees (256 threads)
    __shared__ int partial[256];
    const int CH = (NNODES + 255) / 256;   // 196
    int tid = threadIdx.x;
    int start = tid * CH;
    int sum = 0;
    for (int j = 0; j < CH; j++) {
        int idx = start + j;
        if (idx < NNODES) sum += deg[idx];
    }
    partial[tid] = sum;
    __syncthreads();
    for (int d = 1; d < 256; d <<= 1) {
        int t = (tid >= d) ? partial[tid - d] : 0;
        __syncthreads();
        partial[tid] += t;
        __syncthreads();
    }
    int run = (tid == 0) ? 0 : partial[tid - 1];
    for (int j = 0; j < CH; j++) {
        int idx = start + j;
        if (idx < NNODES) {
            off[idx] = run;
            cursor[idx] = run;
            run += deg[idx];
        }
    }
    if (tid == 255) off[NNODES] = NEDGES;
}

// ---------------------------------------------------------------------------
// K3: fill CSC
// ---------------------------------------------------------------------------
__global__ void fill_csc(const int* __restrict__ row,
                         const int* __restrict__ col,
                         const float* __restrict__ w,
                         const float* __restrict__ ws,
                         int* __restrict__ cursor,
                         int2* __restrict__ edge) {
    int i = blockIdx.x * blockDim.x + threadIdx.x;
    if (i < NEDGES) {
        int r = row[i];
        int c = col[i];
        float wn = 0.9f * w[i] / fmaxf(ws[r], 1.0f);
        int pos = atomicAdd(&cursor[c], 1);
        edge[pos] = make_int2(r, __float_as_int(wn));
    }
}

// ---------------------------------------------------------------------------
// Propagation gather step — half-warp per edge, LDG.128, fp16 anchor.
// ---------------------------------------------------------------------------
__device__ __forceinline__ void acc8(float* a, uint4 p, float wgt) {
    float2 t0 = __half22float2(*(__half2*)&p.x);
    float2 t1 = __half22float2(*(__half2*)&p.y);
    float2 t2 = __half22float2(*(__half2*)&p.z);
    float2 t3 = __half22float2(*(__half2*)&p.w);
    a[0] += wgt * t0.x; a[1] += wgt * t0.y;
    a[2] += wgt * t1.x; a[3] += wgt * t1.y;
    a[4] += wgt * t2.x; a[5] += wgt * t2.y;
    a[6] += wgt * t3.x; a[7] += wgt * t3.y;
}

template <bool FIN, bool WRITE>
__global__ void prop_gather_h(const __half* __restrict__ src16,
                              const __half* __restrict__ anc16,
                              __half* __restrict__ dst16,
                              const int* __restrict__ off,
                              const int2* __restrict__ edge,
                              float* __restrict__ F,
                              const float* __restrict__ sw, int swIdx) {
    int warp = (blockIdx.x * blockDim.x + threadIdx.x) >> 5;
    if (warp >= NNODES) return;
    int lane = threadIdx.x & 31;
    int halfe = lane >> 4;    // which edge of the pair
    int hl    = lane & 15;    // feature chunk within the row (8 fp16)

    int s = __ldg(off + warp);
    int e = __ldg(off + warp + 1);
    int npair = (e - s + 1) >> 1;

    float a[8];
#pragma unroll
    for (int j = 0; j < 8; j++) a[j] = 0.f;

    int it = 0;
    for (; it + 4 <= npair; it += 4) {
        int b0 = s + 2 * it + halfe;
        int2 e0 = (b0     < e) ? __ldg(edge + b0)     : make_int2(0, 0);
        int2 e1 = (b0 + 2 < e) ? __ldg(edge + b0 + 2) : make_int2(0, 0);
        int2 e2 = (b0 + 4 < e) ? __ldg(edge + b0 + 4) : make_int2(0, 0);
        int2 e3 = (b0 + 6 < e) ? __ldg(edge + b0 + 6) : make_int2(0, 0);
        uint4 p0 = __ldg((const uint4*)(src16 + (size_t)e0.x * HDIM) + hl);
        uint4 p1 = __ldg((const uint4*)(src16 + (size_t)e1.x * HDIM) + hl);
        uint4 p2 = __ldg((const uint4*)(src16 + (size_t)e2.x * HDIM) + hl);
        uint4 p3 = __ldg((const uint4*)(src16 + (size_t)e3.x * HDIM) + hl);
        acc8(a, p0, __int_as_float(e0.y));
        acc8(a, p1, __int_as_float(e1.y));
        acc8(a, p2, __int_as_float(e2.y));
        acc8(a, p3, __int_as_float(e3.y));
    }
    for (; it < npair; it++) {
        int b0 = s + 2 * it + halfe;
        int2 e0 = (b0 < e) ? __ldg(edge + b0) : make_int2(0, 0);
        uint4 p0 = __ldg((const uint4*)(src16 + (size_t)e0.x * HDIM) + hl);
        acc8(a, p0, __int_as_float(e0.y));
    }

#pragma unroll
    for (int j = 0; j < 8; j++)
        a[j] += __shfl_down_sync(0xffffffffu, a[j], 16);

    if (halfe == 0) {
        uint4 hp = __ldg((const uint4*)(anc16 + (size_t)warp * HDIM) + hl);
        float2 h0 = __half22float2(*(__half2*)&hp.x);
        float2 h1 = __half22float2(*(__half2*)&hp.y);
        float2 h2 = __half22float2(*(__half2*)&hp.z);
        float2 h3 = __half22float2(*(__half2*)&hp.w);
        a[0] += 0.1f * h0.x; a[1] += 0.1f * h0.y;
        a[2] += 0.1f * h1.x; a[3] += 0.1f * h1.y;
        a[4] += 0.1f * h2.x; a[5] += 0.1f * h2.y;
        a[6] += 0.1f * h3.x; a[7] += 0.1f * h3.y;

        if (WRITE) {
            __half2 o0 = __floats2half2_rn(a[0], a[1]);
            __half2 o1 = __floats2half2_rn(a[2], a[3]);
            __half2 o2 = __floats2half2_rn(a[4], a[5]);
            __half2 o3 = __floats2half2_rn(a[6], a[7]);
            uint4 ov = make_uint4(*(unsigned*)&o0, *(unsigned*)&o1,
                                  *(unsigned*)&o2, *(unsigned*)&o3);
            *((uint4*)(dst16 + (size_t)warp * HDIM) + hl) = ov;
        }
        if (FIN) {
            float fw = __ldg(sw + swIdx);
            float4* fp = (float4*)(F + (size_t)warp * HDIM) + hl * 2;
            float4 f0 = fp[0], f1 = fp[1];
            f0.x += fw * a[0]; f0.y += fw * a[1]; f0.z += fw * a[2]; f0.w += fw * a[3];
            f1.x += fw * a[4]; f1.y += fw * a[5]; f1.z += fw * a[6]; f1.w += fw * a[7];
            fp[0] = f0; fp[1] = f1;
        }
    }
}

// ---------------------------------------------------------------------------
// Head: out = relu(bn3(F@W3 + b3)) @ W4 + b4   — one warp per node.
// Also re-zeroes ws/deg so the next launch (graph replay) starts clean.
// ---------------------------------------------------------------------------
__global__ void head_kernel(const float* __restrict__ F,
                            const float* __restrict__ W3, const float* __restrict__ b3,
                            const float* __restrict__ g3, const float* __restrict__ be3,
                            const float* __restrict__ m3, const float* __restrict__ v3,
                            const float* __restrict__ W4, const float* __restrict__ b4,
                            float* __restrict__ out,
                            float* __restrict__ ws, int* __restrict__ deg) {
    __shared__ float sW3[HDIM * H2DIM];
    __shared__ float sW4[H2DIM * ODIM];
    __shared__ float sS3[H2DIM], sSh3[H2DIM], sB4[ODIM];
    __shared__ float fr[8][HDIM];
    __shared__ float hid[8][H2DIM];

    int tid = threadIdx.x;
    // re-zero for next replay (no intra-launch consumer after this point)
    for (int i = blockIdx.x * blockDim.x + tid; i < NNODES; i += gridDim.x * blockDim.x) {
        ws[i] = 0.f; deg[i] = 0;
    }

    for (int i = tid; i < HDIM * H2DIM; i += blockDim.x) sW3[i] = W3[i];
    for (int i = tid; i < H2DIM * ODIM; i += blockDim.x) sW4[i] = W4[i];
    if (tid < H2DIM) {
        float s = g3[tid] * rsqrtf(v3[tid] + EPS);
        sS3[tid] = s;
        sSh3[tid] = (b3[tid] - m3[tid]) * s + be3[tid];
    }
    if (tid < ODIM) sB4[tid] = b4[tid];
    __syncthreads();

    int warp = tid >> 5, lane = tid & 31;
    int nwarps = blockDim.x >> 5;
    for (int n = blockIdx.x * nwarps + warp; n < NNODES; n += gridDim.x * nwarps) {
        ((float4*)fr[warp])[lane] = ((const float4*)(F + (size_t)n * HDIM))[lane];
        __syncwarp();
#pragma unroll
        for (int hh = 0; hh < 2; hh++) {
            int j = lane + 32 * hh;
            float acc = 0.f;
#pragma unroll 8
            for (int k = 0; k < HDIM; k++) acc += fr[warp][k] * sW3[k * H2DIM + j];
            hid[warp][j] = fmaxf(acc * sS3[j] + sSh3[j], 0.f);
        }
        __syncwarp();
        float acc = sB4[lane];
#pragma unroll 8
        for (int j = 0; j < H2DIM; j++) acc += hid[warp][j] * sW4[j * ODIM + lane];
        out[(size_t)n * ODIM + lane] = acc;
        __syncwarp();
    }
}

// ---------------------------------------------------------------------------
// Launch
// ---------------------------------------------------------------------------
extern "C" void kernel_launch(void* const* d_in, const int* in_sizes, int n_in,
                              void* d_out, int out_size) {
    const float* x   = (const float*)d_in[0];
    const int*   ei  = (const int*)d_in[1];
    const float* ew  = (const float*)d_in[2];
    const float* W1  = (const float*)d_in[3];
    const float* b1  = (const float*)d_in[4];
    const float* g1  = (const float*)d_in[5];
    const float* be1 = (const float*)d_in[6];
    const float* m1  = (const float*)d_in[7];
    const float* v1  = (const float*)d_in[8];
    const float* W2  = (const float*)d_in[9];
    const float* b2  = (const float*)d_in[10];
    const float* g2  = (const float*)d_in[11];
    const float* be2 = (const float*)d_in[12];
    const float* m2  = (const float*)d_in[13];
    const float* v2  = (const float*)d_in[14];
    const float* att = (const float*)d_in[15];
    const float* W3  = (const float*)d_in[16];
    const float* b3  = (const float*)d_in[17];
    const float* g3  = (const float*)d_in[18];
    const float* be3 = (const float*)d_in[19];
    const float* m3  = (const float*)d_in[20];
    const float* v3  = (const float*)d_in[21];
    const float* W4  = (const float*)d_in[22];
    const float* b4  = (const float*)d_in[23];

    const int* row = ei;
    const int* col = ei + NEDGES;

    float *B1, *F, *WS, *SW;
    __half* HB[3];
    int *DEG, *CUR, *OFF;
    int2 *EDGE;
    cudaGetSymbolAddress((void**)&B1,    gB1);
    cudaGetSymbolAddress((void**)&F,     gFz);
    cudaGetSymbolAddress((void**)&HB[0], gH0);
    cudaGetSymbolAddress((void**)&HB[1], gH1);
    cudaGetSymbolAddress((void**)&HB[2], gH2);
    cudaGetSymbolAddress((void**)&WS,    gWsum);
    cudaGetSymbolAddress((void**)&DEG,   gDeg);
    cudaGetSymbolAddress((void**)&CUR,   gCur);
    cudaGetSymbolAddress((void**)&OFF,   gOff);
    cudaGetSymbolAddress((void**)&EDGE,  gEdge);
    cudaGetSymbolAddress((void**)&SW,    gSw);

    const int edgeBlocks = (NEDGES + 255) / 256;
    const int propBlocks = (NNODES * 32 + 255) / 256;

    // K1: GEMM1 + wsum/deg + softmax (ws/deg are zero on entry: static init
    // on first call, trailing re-zero in head_kernel on subsequent replays)
    k1_gemm1_wsum<<<GEMM_BLOCKS + WS_BLOCKS, 256>>>(
        x, W1, b1, g1, be1, m1, v1, B1, row, col, ew, WS, DEG, att, SW);

    // K2: GEMM2 (fp16 state + F=sw0*hc) + degree scan
    k2_gemm2_scan<<<GEMM_BLOCKS + 1, 256>>>(
        B1, W2, b2, g2, be2, m2, v2, HB[0], F, SW, DEG, OFF, CUR);

    // K3: fill CSC
    fill_csc<<<edgeBlocks, 256>>>(row, col, ew, WS, CUR, EDGE);

    // K4..K28: propagation (25 steps, 3 rotating fp16 buffers)
    int anci = 0, curi = 0;
    for (int k = 0; k < KHOPS; k++) {
        anci = curi;
        for (int t = 0; t < KHOPS; t++) {
            int dsti = 0;
            for (int d = 0; d < 3; d++)
                if (d != anci && d != curi) dsti = d;
            bool fin  = (t == KHOPS - 1);
            bool last = (fin && k == KHOPS - 1);
            if (last)
                prop_gather_h<true,  false><<<propBlocks, 256>>>(
                    HB[curi], HB[anci], HB[dsti], OFF, EDGE, F, SW, k + 1);
            else if (fin)
                prop_gather_h<true,  true ><<<propBlocks, 256>>>(
                    HB[curi], HB[anci], HB[dsti], OFF, EDGE, F, SW, k + 1);
            else
                prop_gather_h<false, true ><<<propBlocks, 256>>>(
                    HB[curi], HB[anci], HB[dsti], OFF, EDGE, nullptr, SW, 0);
            curi = dsti;
        }
    }

    // K29: head (+ trailing ws/deg re-zero)
    head_kernel<<<1184, 256>>>(F, W3, b3, g3, be3, m3, v3, W4, b4,
                               (float*)d_out, WS, DEG);
}

// round 8
// speedup vs baseline: 1.1727x; 1.1445x over previous
#include <cuda_runtime.h>
#include <cuda_fp16.h>
#include <cuda_bf16.h>

// Problem constants
#define NNODES 50000
#define NEDGES 800000
#define IN_DIM 256
#define HDIM   128
#define H2DIM  64
#define ODIM   32
#define KHOPS  5
#define EPS    1e-5f

#define GEMM_BLOCKS ((NNODES + 63) / 64)   // 782
#define WS_BLOCKS   160                    // extra blocks in K1 for wsum/deg
#define PADCAP      (NEDGES + 8 * NNODES)  // padded edge capacity

// ---------------------------------------------------------------------------
// Scratch (device globals; zero-initialized at module load).
// gWsum/gDeg re-zeroed at END of every launch (head_kernel) for graph replay.
// ---------------------------------------------------------------------------
__device__ float  gB1[NNODES * HDIM];      // GEMM1 output
__device__ float  gFz[NNODES * HDIM];      // fused accumulator
__device__ __half gH0[NNODES * HDIM];      // fp16 state buffers (rotating)
__device__ __half gH1[NNODES * HDIM];
__device__ __half gH2[NNODES * HDIM];
__device__ float  gWsum[NNODES];
__device__ int    gDeg[NNODES];
__device__ int    gCur[NNODES];
__device__ int    gOff[NNODES + 1];
__device__ int2   gEdge[PADCAP];           // {src, __float_as_int(weight)}
__device__ float  gSw[8];

// ---------------------------------------------------------------------------
// Tiled fp32 GEMM body (device function; block role decided by caller).
// ---------------------------------------------------------------------------
template <int KDIM, bool RES, bool FUSEP>
__device__ __forceinline__ void gemm_body(
    int bx,
    const float* __restrict__ A,
    const float* __restrict__ W,
    const float* __restrict__ bias,
    const float* __restrict__ g,
    const float* __restrict__ be,
    const float* __restrict__ m,
    const float* __restrict__ v,
    const float* __restrict__ ident,
    float* __restrict__ out32,
    __half* __restrict__ out16,
    float* __restrict__ F,
    const float* __restrict__ sw, int M) {
    __shared__ float  As[64][17];
    __shared__ float4 Bs[16][32];
    const int tid = threadIdx.x;
    const int rowBase = bx * 64;
    const int cg = tid & 31;
    const int rg = tid >> 5;

    float acc[8][4];
#pragma unroll
    for (int i = 0; i < 8; i++)
#pragma unroll
        for (int j = 0; j < 4; j++) acc[i][j] = 0.f;

    for (int k0 = 0; k0 < KDIM; k0 += 16) {
        {
            int r = tid >> 2, c4 = tid & 3;
            float4 val = make_float4(0.f, 0.f, 0.f, 0.f);
            if (rowBase + r < M)
                val = *(const float4*)(A + (size_t)(rowBase + r) * KDIM + k0 + c4 * 4);
            As[r][c4 * 4 + 0] = val.x; As[r][c4 * 4 + 1] = val.y;
            As[r][c4 * 4 + 2] = val.z; As[r][c4 * 4 + 3] = val.w;
        }
#pragma unroll
        for (int i = tid; i < 512; i += 256) {
            int r = i >> 5, c = i & 31;
            Bs[r][c] = *(const float4*)(W + (size_t)(k0 + r) * HDIM + c * 4);
        }
        __syncthreads();
#pragma unroll
        for (int kk = 0; kk < 16; kk++) {
            float a[8];
#pragma unroll
            for (int i = 0; i < 8; i++) a[i] = As[rg * 8 + i][kk];
            float4 b = Bs[kk][cg];
#pragma unroll
            for (int i = 0; i < 8; i++) {
                acc[i][0] += a[i] * b.x; acc[i][1] += a[i] * b.y;
                acc[i][2] += a[i] * b.z; acc[i][3] += a[i] * b.w;
            }
        }
        __syncthreads();
    }

    float s[4], sh[4], bb[4];
#pragma unroll
    for (int j = 0; j < 4; j++) {
        int c = cg * 4 + j;
        s[j]  = g[c] * rsqrtf(v[c] + EPS);
        sh[j] = be[c] - m[c] * s[j];
        bb[j] = bias[c];
    }
    float fw = FUSEP ? __ldg(sw) : 0.f;
#pragma unroll
    for (int i = 0; i < 8; i++) {
        int rr = rowBase + rg * 8 + i;
        if (rr < M) {
            float4 o;
            o.x = fmaxf((acc[i][0] + bb[0]) * s[0] + sh[0], 0.f);
            o.y = fmaxf((acc[i][1] + bb[1]) * s[1] + sh[1], 0.f);
            o.z = fmaxf((acc[i][2] + bb[2]) * s[2] + sh[2], 0.f);
            o.w = fmaxf((acc[i][3] + bb[3]) * s[3] + sh[3], 0.f);
            if (RES) {
                float4 r4 = *(const float4*)(ident + (size_t)rr * HDIM + cg * 4);
                o.x += r4.x; o.y += r4.y; o.z += r4.z; o.w += r4.w;
            }
            if (FUSEP) {
                __half2 h0 = __floats2half2_rn(o.x, o.y);
                __half2 h1 = __floats2half2_rn(o.z, o.w);
                uint2 hv = make_uint2(*(unsigned*)&h0, *(unsigned*)&h1);
                ((uint2*)(out16 + (size_t)rr * HDIM))[cg] = hv;
                float4 f = make_float4(fw * o.x, fw * o.y, fw * o.z, fw * o.w);
                *(float4*)(F + (size_t)rr * HDIM + cg * 4) = f;
            } else {
                *(float4*)(out32 + (size_t)rr * HDIM + cg * 4) = o;
            }
        }
    }
}

// ---------------------------------------------------------------------------
// K1: GEMM1 + (tail blocks) wsum/deg accumulation + softmax(att)
// ---------------------------------------------------------------------------
__global__ void k1_gemm1_wsum(const float* __restrict__ x,
                              const float* __restrict__ W1,
                              const float* __restrict__ b1,
                              const float* __restrict__ g1,
                              const float* __restrict__ be1,
                              const float* __restrict__ m1,
                              const float* __restrict__ v1,
                              float* __restrict__ out32,
                              const int* __restrict__ row,
                              const int* __restrict__ col,
                              const float* __restrict__ ew,
                              float* __restrict__ ws,
                              int* __restrict__ deg,
                              const float* __restrict__ att,
                              float* __restrict__ sw) {
    int bx = blockIdx.x;
    if (bx < GEMM_BLOCKS) {
        gemm_body<IN_DIM, false, false>(bx, x, W1, b1, g1, be1, m1, v1,
                                        nullptr, out32, nullptr, nullptr, nullptr, NNODES);
        return;
    }
    int ebx = bx - GEMM_BLOCKS;
    for (int i = ebx * 256 + threadIdx.x; i < NEDGES; i += WS_BLOCKS * 256) {
        atomicAdd(&ws[row[i]], ew[i]);
        atomicAdd(&deg[col[i]], 1);
    }
    if (ebx == WS_BLOCKS - 1 && threadIdx.x == 0) {
        float mx = -1e30f;
        for (int i = 0; i < KHOPS + 1; i++) mx = fmaxf(mx, att[i]);
        float e[KHOPS + 1], sum = 0.f;
        for (int i = 0; i < KHOPS + 1; i++) { e[i] = expf(att[i] - mx); sum += e[i]; }
        for (int i = 0; i < KHOPS + 1; i++) sw[i] = e[i] / sum;
    }
}

// ---------------------------------------------------------------------------
// K2: GEMM2 (+ fp16 state + F init) + (1 tail block) PADDED offset scan
// off[i] = prefix sum of padded degrees ((deg+7)&~7); cursor = off.
// ---------------------------------------------------------------------------
__global__ void k2_gemm2_scan(const float* __restrict__ h1,
                              const float* __restrict__ W2,
                              const float* __restrict__ b2,
                              const float* __restrict__ g2,
                              const float* __restrict__ be2,
                              const float* __restrict__ m2,
                              const float* __restrict__ v2,
                              __half* __restrict__ out16,
                              float* __restrict__ F,
                              const float* __restrict__ sw,
                              const int* __restrict__ deg,
                              int* __restrict__ off,
                              int* __restrict__ cursor) {
    int bx = blockIdx.x;
    if (bx < GEMM_BLOCKS) {
        gemm_body<HDIM, true, true>(bx, h1, W2, b2, g2, be2, m2, v2,
                                    h1, nullptr, out16, F, sw, NNODES);
        return;
    }
    __shared__ int partial[256];
    const int CH = (NNODES + 255) / 256;   // 196
    int tid = threadIdx.x;
    int start = tid * CH;
    int sum = 0;
    for (int j = 0; j < CH; j++) {
        int idx = start + j;
        if (idx < NNODES) sum += (deg[idx] + 7) & ~7;
    }
    partial[tid] = sum;
    __syncthreads();
    for (int d = 1; d < 256; d <<= 1) {
        int t = (tid >= d) ? partial[tid - d] : 0;
        __syncthreads();
        partial[tid] += t;
        __syncthreads();
    }
    int run = (tid == 0) ? 0 : partial[tid - 1];
    for (int j = 0; j < CH; j++) {
        int idx = start + j;
        if (idx < NNODES) {
            off[idx] = run;
            cursor[idx] = run;
            run += (deg[idx] + 7) & ~7;
        }
    }
    if (tid == 255) off[NNODES] = partial[255];
}

// ---------------------------------------------------------------------------
// K3: fill CSC (edge blocks) + pad fill (node tail blocks).
// Pad entries: {src=0, w=0} — memory-free (row 0 stays L1-hot), math-neutral.
// ---------------------------------------------------------------------------
#define EDGE_BLOCKS ((NEDGES + 255) / 256)
#define NODE_BLOCKS ((NNODES + 255) / 256)

__global__ void fill_csc_pad(const int* __restrict__ row,
                             const int* __restrict__ col,
                             const float* __restrict__ w,
                             const float* __restrict__ ws,
                             const int* __restrict__ deg,
                             const int* __restrict__ off,
                             int* __restrict__ cursor,
                             int2* __restrict__ edge) {
    int bx = blockIdx.x;
    if (bx < EDGE_BLOCKS) {
        int i = bx * 256 + threadIdx.x;
        if (i < NEDGES) {
            int r = row[i];
            int c = col[i];
            float wn = 0.9f * w[i] / fmaxf(ws[r], 1.0f);
            int pos = atomicAdd(&cursor[c], 1);
            edge[pos] = make_int2(r, __float_as_int(wn));
        }
        return;
    }
    int n = (bx - EDGE_BLOCKS) * 256 + threadIdx.x;
    if (n < NNODES) {
        int d = deg[n];
        int s = off[n] + d;
        int e = off[n] + ((d + 7) & ~7);
        for (int p = s; p < e; p++) edge[p] = make_int2(0, 0);
    }
}

// ---------------------------------------------------------------------------
// Propagation gather — half-warp per edge, LDG.128, padded (no predicates).
// ---------------------------------------------------------------------------
__device__ __forceinline__ void acc8(float* a, uint4 p, float wgt) {
    float2 t0 = __half22float2(*(__half2*)&p.x);
    float2 t1 = __half22float2(*(__half2*)&p.y);
    float2 t2 = __half22float2(*(__half2*)&p.z);
    float2 t3 = __half22float2(*(__half2*)&p.w);
    a[0] += wgt * t0.x; a[1] += wgt * t0.y;
    a[2] += wgt * t1.x; a[3] += wgt * t1.y;
    a[4] += wgt * t2.x; a[5] += wgt * t2.y;
    a[6] += wgt * t3.x; a[7] += wgt * t3.y;
}

template <bool FIN, bool WRITE>
__global__ void prop_gather_h(const __half* __restrict__ src16,
                              const __half* __restrict__ anc16,
                              __half* __restrict__ dst16,
                              const int* __restrict__ off,
                              const int2* __restrict__ edge,
                              float* __restrict__ F,
                              const float* __restrict__ sw, int swIdx) {
    int warp = (blockIdx.x * blockDim.x + threadIdx.x) >> 5;
    if (warp >= NNODES) return;
    int lane = threadIdx.x & 31;
    int halfe = lane >> 4;    // which edge of the pair
    int hl    = lane & 15;    // feature chunk within the row (8 fp16)

    int s = __ldg(off + warp);
    int e = __ldg(off + warp + 1);   // e - s is a multiple of 8

    float a[8];
#pragma unroll
    for (int j = 0; j < 8; j++) a[j] = 0.f;

    for (int i = s + halfe; i < e; i += 8) {
        int2 e0 = __ldg(edge + i);
        int2 e1 = __ldg(edge + i + 2);
        int2 e2 = __ldg(edge + i + 4);
        int2 e3 = __ldg(edge + i + 6);
        uint4 p0 = __ldg((const uint4*)(src16 + (size_t)e0.x * HDIM) + hl);
        uint4 p1 = __ldg((const uint4*)(src16 + (size_t)e1.x * HDIM) + hl);
        uint4 p2 = __ldg((const uint4*)(src16 + (size_t)e2.x * HDIM) + hl);
        uint4 p3 = __ldg((const uint4*)(src16 + (size_t)e3.x * HDIM) + hl);
        acc8(a, p0, __int_as_float(e0.y));
        acc8(a, p1, __int_as_float(e1.y));
        acc8(a, p2, __int_as_float(e2.y));
        acc8(a, p3, __int_as_float(e3.y));
    }

#pragma unroll
    for (int j = 0; j < 8; j++)
        a[j] += __shfl_down_sync(0xffffffffu, a[j], 16);

    if (halfe == 0) {
        uint4 hp = __ldg((const uint4*)(anc16 + (size_t)warp * HDIM) + hl);
        float2 h0 = __half22float2(*(__half2*)&hp.x);
        float2 h1 = __half22float2(*(__half2*)&hp.y);
        float2 h2 = __half22float2(*(__half2*)&hp.z);
        float2 h3 = __half22float2(*(__half2*)&hp.w);
        a[0] += 0.1f * h0.x; a[1] += 0.1f * h0.y;
        a[2] += 0.1f * h1.x; a[3] += 0.1f * h1.y;
        a[4] += 0.1f * h2.x; a[5] += 0.1f * h2.y;
        a[6] += 0.1f * h3.x; a[7] += 0.1f * h3.y;

        if (WRITE) {
            __half2 o0 = __floats2half2_rn(a[0], a[1]);
            __half2 o1 = __floats2half2_rn(a[2], a[3]);
            __half2 o2 = __floats2half2_rn(a[4], a[5]);
            __half2 o3 = __floats2half2_rn(a[6], a[7]);
            uint4 ov = make_uint4(*(unsigned*)&o0, *(unsigned*)&o1,
                                  *(unsigned*)&o2, *(unsigned*)&o3);
            *((uint4*)(dst16 + (size_t)warp * HDIM) + hl) = ov;
        }
        if (FIN) {
            float fw = __ldg(sw + swIdx);
            float4* fp = (float4*)(F + (size_t)warp * HDIM) + hl * 2;
            float4 f0 = fp[0], f1 = fp[1];
            f0.x += fw * a[0]; f0.y += fw * a[1]; f0.z += fw * a[2]; f0.w += fw * a[3];
            f1.x += fw * a[4]; f1.y += fw * a[5]; f1.z += fw * a[6]; f1.w += fw * a[7];
            fp[0] = f0; fp[1] = f1;
        }
    }
}

// ---------------------------------------------------------------------------
// Head: out = relu(bn3(F@W3 + b3)) @ W4 + b4  — one warp per node.
// Also re-zeroes ws/deg for the next graph replay.
// ---------------------------------------------------------------------------
__global__ void head_kernel(const float* __restrict__ F,
                            const float* __restrict__ W3, const float* __restrict__ b3,
                            const float* __restrict__ g3, const float* __restrict__ be3,
                            const float* __restrict__ m3, const float* __restrict__ v3,
                            const float* __restrict__ W4, const float* __restrict__ b4,
                            float* __restrict__ out,
                            float* __restrict__ ws, int* __restrict__ deg) {
    __shared__ float sW3[HDIM * H2DIM];
    __shared__ float sW4[H2DIM * ODIM];
    __shared__ float sS3[H2DIM], sSh3[H2DIM], sB4[ODIM];
    __shared__ float fr[8][HDIM];
    __shared__ float hid[8][H2DIM];

    int tid = threadIdx.x;
    for (int i = blockIdx.x * blockDim.x + tid; i < NNODES; i += gridDim.x * blockDim.x) {
        ws[i] = 0.f; deg[i] = 0;
    }

    for (int i = tid; i < HDIM * H2DIM; i += blockDim.x) sW3[i] = W3[i];
    for (int i = tid; i < H2DIM * ODIM; i += blockDim.x) sW4[i] = W4[i];
    if (tid < H2DIM) {
        float s = g3[tid] * rsqrtf(v3[tid] + EPS);
        sS3[tid] = s;
        sSh3[tid] = (b3[tid] - m3[tid]) * s + be3[tid];
    }
    if (tid < ODIM) sB4[tid] = b4[tid];
    __syncthreads();

    int warp = tid >> 5, lane = tid & 31;
    int nwarps = blockDim.x >> 5;
    for (int n = blockIdx.x * nwarps + warp; n < NNODES; n += gridDim.x * nwarps) {
        ((float4*)fr[warp])[lane] = ((const float4*)(F + (size_t)n * HDIM))[lane];
        __syncwarp();
#pragma unroll
        for (int hh = 0; hh < 2; hh++) {
            int j = lane + 32 * hh;
            float acc = 0.f;
#pragma unroll 8
            for (int k = 0; k < HDIM; k++) acc += fr[warp][k] * sW3[k * H2DIM + j];
            hid[warp][j] = fmaxf(acc * sS3[j] + sSh3[j], 0.f);
        }
        __syncwarp();
        float acc = sB4[lane];
#pragma unroll 8
        for (int j = 0; j < H2DIM; j++) acc += hid[warp][j] * sW4[j * ODIM + lane];
        out[(size_t)n * ODIM + lane] = acc;
        __syncwarp();
    }
}

// ---------------------------------------------------------------------------
// Launch
// ---------------------------------------------------------------------------
extern "C" void kernel_launch(void* const* d_in, const int* in_sizes, int n_in,
                              void* d_out, int out_size) {
    const float* x   = (const float*)d_in[0];
    const int*   ei  = (const int*)d_in[1];
    const float* ew  = (const float*)d_in[2];
    const float* W1  = (const float*)d_in[3];
    const float* b1  = (const float*)d_in[4];
    const float* g1  = (const float*)d_in[5];
    const float* be1 = (const float*)d_in[6];
    const float* m1  = (const float*)d_in[7];
    const float* v1  = (const float*)d_in[8];
    const float* W2  = (const float*)d_in[9];
    const float* b2  = (const float*)d_in[10];
    const float* g2  = (const float*)d_in[11];
    const float* be2 = (const float*)d_in[12];
    const float* m2  = (const float*)d_in[13];
    const float* v2  = (const float*)d_in[14];
    const float* att = (const float*)d_in[15];
    const float* W3  = (const float*)d_in[16];
    const float* b3  = (const float*)d_in[17];
    const float* g3  = (const float*)d_in[18];
    const float* be3 = (const float*)d_in[19];
    const float* m3  = (const float*)d_in[20];
    const float* v3  = (const float*)d_in[21];
    const float* W4  = (const float*)d_in[22];
    const float* b4  = (const float*)d_in[23];

    const int* row = ei;
    const int* col = ei + NEDGES;

    float *B1, *F, *WS, *SW;
    __half* HB[3];
    int *DEG, *CUR, *OFF;
    int2 *EDGE;
    cudaGetSymbolAddress((void**)&B1,    gB1);
    cudaGetSymbolAddress((void**)&F,     gFz);
    cudaGetSymbolAddress((void**)&HB[0], gH0);
    cudaGetSymbolAddress((void**)&HB[1], gH1);
    cudaGetSymbolAddress((void**)&HB[2], gH2);
    cudaGetSymbolAddress((void**)&WS,    gWsum);
    cudaGetSymbolAddress((void**)&DEG,   gDeg);
    cudaGetSymbolAddress((void**)&CUR,   gCur);
    cudaGetSymbolAddress((void**)&OFF,   gOff);
    cudaGetSymbolAddress((void**)&EDGE,  gEdge);
    cudaGetSymbolAddress((void**)&SW,    gSw);

    const int propBlocks = (NNODES * 32 + 255) / 256;

    // K1: GEMM1 + wsum/deg + softmax
    k1_gemm1_wsum<<<GEMM_BLOCKS + WS_BLOCKS, 256>>>(
        x, W1, b1, g1, be1, m1, v1, B1, row, col, ew, WS, DEG, att, SW);

    // K2: GEMM2 (fp16 state + F=sw0*hc) + padded degree scan
    k2_gemm2_scan<<<GEMM_BLOCKS + 1, 256>>>(
        B1, W2, b2, g2, be2, m2, v2, HB[0], F, SW, DEG, OFF, CUR);

    // K3: fill CSC + padding
    fill_csc_pad<<<EDGE_BLOCKS + NODE_BLOCKS, 256>>>(
        row, col, ew, WS, DEG, OFF, CUR, EDGE);

    // K4..K28: propagation (25 steps, 3 rotating fp16 buffers)
    int anci = 0, curi = 0;
    for (int k = 0; k < KHOPS; k++) {
        anci = curi;
        for (int t = 0; t < KHOPS; t++) {
            int dsti = 0;
            for (int d = 0; d < 3; d++)
                if (d != anci && d != curi) dsti = d;
            bool fin  = (t == KHOPS - 1);
            bool last = (fin && k == KHOPS - 1);
            if (last)
                prop_gather_h<true,  false><<<propBlocks, 256>>>(
                    HB[curi], HB[anci], HB[dsti], OFF, EDGE, F, SW, k + 1);
            else if (fin)
                prop_gather_h<true,  true ><<<propBlocks, 256>>>(
                    HB[curi], HB[anci], HB[dsti], OFF, EDGE, F, SW, k + 1);
            else
                prop_gather_h<false, true ><<<propBlocks, 256>>>(
                    HB[curi], HB[anci], HB[dsti], OFF, EDGE, nullptr, SW, 0);
            curi = dsti;
        }
    }

    // K29: head (+ trailing ws/deg re-zero)
    head_kernel<<<1184, 256>>>(F, W3, b3, g3, be3, m3, v3, W4, b4,
                               (float*)d_out, WS, DEG);
}